// round 6
// baseline (speedup 1.0000x reference)
#include <cuda_runtime.h>
#include <math.h>

#define BATCH   8
#define TLEN    16384
#define NPOS    (BATCH*TLEN)     // 131072
#define RC      32
#define CIN     256
#define COUT    256
#define NLAYERS 40
#define TILE    128
#define NTILES  (NPOS/TILE)      // 1024
#define LGRID   (NTILES/2)       // 512: 2 tiles per block -> single wave

typedef unsigned long long u64;

__device__ float g_h[2][RC * NPOS];
__device__ float g_skip[RC * NPOS];

__device__ __forceinline__ u64 pack2(float lo, float hi) {
    u64 r; asm("mov.b64 %0, {%1, %2};" : "=l"(r) : "f"(lo), "f"(hi)); return r;
}
__device__ __forceinline__ u64 dup2(float x) {
    u64 r; asm("mov.b64 %0, {%1, %1};" : "=l"(r) : "f"(x)); return r;
}
__device__ __forceinline__ void unpack2(u64 v, float& lo, float& hi) {
    asm("mov.b64 {%0, %1}, %2;" : "=f"(lo), "=f"(hi) : "l"(v));
}
#define FFMA2(d, a, b) asm("fma.rn.f32x2 %0, %1, %2, %0;" : "+l"(d) : "l"(a), "l"(b))

__device__ __forceinline__ float htanh(float x) {
    float y; asm("tanh.approx.f32 %0, %1;" : "=f"(y) : "f"(x)); return y;
}
// tanh(c) * sigmoid(g) = 0.5*tanh(c)*(1 + tanh(0.5*g))
__device__ __forceinline__ float gated(float c, float g) {
    float t1 = htanh(c);
    float t2 = htanh(0.5f * g);
    float ht = 0.5f * t1;
    return fmaf(ht, t2, ht);
}

// ---------------------------------------------------------------------------
// Input 1x1 conv
// ---------------------------------------------------------------------------
__global__ __launch_bounds__(256) void k_input(
    const float* __restrict__ x, const float* __restrict__ w,
    const float* __restrict__ b, float* __restrict__ hout)
{
    __shared__ float ws[CIN][RC];
    __shared__ float bs[RC];
    int tid = threadIdx.x;
    for (int idx = tid; idx < CIN * RC; idx += 256) {
        int o = idx / CIN, ic = idx % CIN;
        ws[ic][o] = w[idx];
    }
    if (tid < RC) bs[tid] = b[tid];
    __syncthreads();

    int p  = blockIdx.x * 256 + tid;
    int bb = p >> 14;
    int t  = p & (TLEN - 1);
    const float* xp = x + ((size_t)bb * CIN) * TLEN + t;

    u64 acc[16];
#pragma unroll
    for (int q = 0; q < 16; q++) acc[q] = pack2(bs[2*q], bs[2*q+1]);

#pragma unroll 4
    for (int ic = 0; ic < CIN; ic++) {
        float xv = __ldg(xp + (size_t)ic * TLEN);
        u64 xd = dup2(xv);
        const ulonglong2* wp = (const ulonglong2*)ws[ic];
#pragma unroll
        for (int q = 0; q < 8; q++) {
            ulonglong2 wv = wp[q];
            FFMA2(acc[2*q],   wv.x, xd);
            FFMA2(acc[2*q+1], wv.y, xd);
        }
    }
#pragma unroll
    for (int q = 0; q < 16; q++) {
        float v0, v1;
        unpack2(acc[q], v0, v1);
        hout[(size_t)(2*q)   * NPOS + p] = v0;
        hout[(size_t)(2*q+1) * NPOS + p] = v1;
    }
}

// ---------------------------------------------------------------------------
// One residual layer. 512 blocks x 2 tiles. 8 warps; warp -> 4 out chans,
// lane -> 4 positions. Weights staged ONCE per block, reused for both tiles.
// ---------------------------------------------------------------------------
__global__ __launch_bounds__(256, 4) void k_layer(
    const float* __restrict__ hin, float* __restrict__ hout,
    float* __restrict__ skip,
    const float* __restrict__ cw, const float* __restrict__ cb,
    const float* __restrict__ gw, const float* __restrict__ gb,
    const float* __restrict__ rw, const float* __restrict__ rb,
    const float* __restrict__ sw, const float* __restrict__ sb,
    int d, int first)
{
    __shared__ float  sh_cur[RC][TILE];   // 16KB
    __shared__ float  sh_pa[RC][TILE];    // 16KB (prev tile, then 'a' tile)
    __shared__ float  swq2[RC][4][RC];    // 16KB [i][kind][o]
    __shared__ float2 swrs2[RC][RC];      //  8KB [i][o] = {rw, sw}

    int tid = threadIdx.x;
    int wid = tid >> 5, l = tid & 31;
    int ow0 = wid * 4;
    int j0  = l * 4;

    // ---- Stage weights once per block ----
    for (int k = tid; k < RC * RC; k += 256) {
        int i = k >> 5, o = k & 31;
        int idx = o * RC + i;
        swq2[i][0][o] = cw[2*idx];
        swq2[i][1][o] = cw[2*idx+1];
        swq2[i][2][o] = gw[2*idx];
        swq2[i][3][o] = gw[2*idx+1];
        swrs2[i][o] = make_float2(rw[idx], sw[idx]);
    }

    // Per-warp bias packs (registers, reused across tiles)
    float4 cbv = *(const float4*)(cb + ow0);
    float4 gbv = *(const float4*)(gb + ow0);
    float4 rbv = *(const float4*)(rb + ow0);
    float4 sbv = *(const float4*)(sb + ow0);
    u64 cbA = pack2(cbv.x, cbv.y), cbB = pack2(cbv.z, cbv.w);
    u64 gbA = pack2(gbv.x, gbv.y), gbB = pack2(gbv.z, gbv.w);
    u64 rsb0 = pack2(rbv.x, sbv.x), rsb1 = pack2(rbv.y, sbv.y);
    u64 rsb2 = pack2(rbv.z, sbv.z), rsb3 = pack2(rbv.w, sbv.w);

#pragma unroll
    for (int tt = 0; tt < 2; tt++) {
        int base = (blockIdx.x + tt * LGRID) * TILE;
        int t0   = base & (TLEN - 1);

        // ---- Stage activation tiles ----
#pragma unroll
        for (int k = tid; k < RC * (TILE/4); k += 256) {
            int row = k >> 5, c4 = k & 31;
            ((float4*)sh_cur[row])[c4] =
                ((const float4*)(hin + (size_t)row * NPOS + base))[c4];
        }
        if (d >= 4) {
#pragma unroll
            for (int k = tid; k < RC * (TILE/4); k += 256) {
                int row = k >> 5, c4 = k & 31;
                int j = c4 * 4;
                float4 v = make_float4(0.f, 0.f, 0.f, 0.f);
                if (t0 + j >= d)
                    v = *(const float4*)(hin + (size_t)row * NPOS + base + j - d);
                ((float4*)sh_pa[row])[c4] = v;
            }
        } else {
            for (int k = tid; k < RC * TILE; k += 256) {
                int row = k >> 7, j = k & 127;
                float v = 0.0f;
                if (t0 + j >= d) v = hin[(size_t)row * NPOS + base + j - d];
                sh_pa[row][j] = v;
            }
        }
        __syncthreads();

        // ---- Phase 1: conv + gate ----
        u64 c01[4], c23[4], g01[4], g23[4];
#pragma unroll
        for (int p = 0; p < 4; p++) { c01[p]=cbA; c23[p]=cbB; g01[p]=gbA; g23[p]=gbB; }

#pragma unroll 4
        for (int i = 0; i < RC; i++) {
            float4 xc4 = *(const float4*)&sh_cur[i][j0];
            float4 xp4 = *(const float4*)&sh_pa[i][j0];
            ulonglong2 wc0 = *(const ulonglong2*)&swq2[i][0][ow0];
            ulonglong2 wc1 = *(const ulonglong2*)&swq2[i][1][ow0];
            ulonglong2 wg0 = *(const ulonglong2*)&swq2[i][2][ow0];
            ulonglong2 wg1 = *(const ulonglong2*)&swq2[i][3][ow0];
            u64 xpd[4] = { dup2(xp4.x), dup2(xp4.y), dup2(xp4.z), dup2(xp4.w) };
            u64 xcd[4] = { dup2(xc4.x), dup2(xc4.y), dup2(xc4.z), dup2(xc4.w) };
#pragma unroll
            for (int p = 0; p < 4; p++) {
                FFMA2(c01[p], wc0.x, xpd[p]);
                FFMA2(c01[p], wc1.x, xcd[p]);
                FFMA2(c23[p], wc0.y, xpd[p]);
                FFMA2(c23[p], wc1.y, xcd[p]);
                FFMA2(g01[p], wg0.x, xpd[p]);
                FFMA2(g01[p], wg1.x, xcd[p]);
                FFMA2(g23[p], wg0.y, xpd[p]);
                FFMA2(g23[p], wg1.y, xcd[p]);
            }
        }

        // ---- Gated activation ----
        float av[4][4];
#pragma unroll
        for (int p = 0; p < 4; p++) {
            float c0,c1,c2,c3,g0,g1,g2,g3;
            unpack2(c01[p], c0, c1); unpack2(c23[p], c2, c3);
            unpack2(g01[p], g0, g1); unpack2(g23[p], g2, g3);
            av[0][p] = gated(c0, g0);
            av[1][p] = gated(c1, g1);
            av[2][p] = gated(c2, g2);
            av[3][p] = gated(c3, g3);
        }

        __syncthreads();
#pragma unroll
        for (int oo = 0; oo < 4; oo++)
            *(float4*)&sh_pa[ow0 + oo][j0] =
                make_float4(av[oo][0], av[oo][1], av[oo][2], av[oo][3]);
        __syncthreads();

        // ---- Phase 2: res + skip ----
        u64 rs[4][4];
#pragma unroll
        for (int p = 0; p < 4; p++) { rs[0][p]=rsb0; rs[1][p]=rsb1; rs[2][p]=rsb2; rs[3][p]=rsb3; }

#pragma unroll 4
        for (int i = 0; i < RC; i++) {
            float4 a4 = *(const float4*)&sh_pa[i][j0];
            ulonglong2 w01 = *(const ulonglong2*)&swrs2[i][ow0];
            ulonglong2 w23 = *(const ulonglong2*)&swrs2[i][ow0 + 2];
            u64 ad[4] = { dup2(a4.x), dup2(a4.y), dup2(a4.z), dup2(a4.w) };
#pragma unroll
            for (int p = 0; p < 4; p++) {
                FFMA2(rs[0][p], w01.x, ad[p]);
                FFMA2(rs[1][p], w01.y, ad[p]);
                FFMA2(rs[2][p], w23.x, ad[p]);
                FFMA2(rs[3][p], w23.y, ad[p]);
            }
        }

        // ---- Writeback ----
#pragma unroll
        for (int oo = 0; oo < 4; oo++) {
            size_t idx = (size_t)(ow0 + oo) * NPOS + base + j0;
            float4 xc = *(const float4*)&sh_cur[ow0 + oo][j0];
            float rv0,sv0,rv1,sv1,rv2,sv2,rv3,sv3;
            unpack2(rs[oo][0], rv0, sv0);
            unpack2(rs[oo][1], rv1, sv1);
            unpack2(rs[oo][2], rv2, sv2);
            unpack2(rs[oo][3], rv3, sv3);
            float4 ho = make_float4(xc.x + rv0, xc.y + rv1, xc.z + rv2, xc.w + rv3);
            *(float4*)&hout[idx] = ho;
            float4 sv = make_float4(sv0, sv1, sv2, sv3);
            if (!first) {
                float4 old = *(const float4*)&skip[idx];
                sv.x += old.x; sv.y += old.y; sv.z += old.z; sv.w += old.w;
            }
            *(float4*)&skip[idx] = sv;
        }
        if (tt == 0) __syncthreads();  // protect smem tiles before restage
    }
}

// ---------------------------------------------------------------------------
// Output head
// ---------------------------------------------------------------------------
__global__ __launch_bounds__(256) void k_final(
    const float* __restrict__ skip,
    const float* __restrict__ w1, const float* __restrict__ b1,
    const float* __restrict__ w2, const float* __restrict__ b2,
    float* __restrict__ out)
{
    __shared__ float ws1[RC * RC];
    __shared__ float ws2t[RC][COUT];
    __shared__ float bs1[RC];
    __shared__ float bs2[COUT];
    int tid = threadIdx.x;
    for (int idx = tid; idx < RC * RC; idx += 256) ws1[idx] = w1[idx];
    for (int idx = tid; idx < COUT * RC; idx += 256) {
        int o = idx / RC, i = idx % RC;
        ws2t[i][o] = w2[idx];
    }
    if (tid < RC) bs1[tid] = b1[tid];
    if (tid < COUT) bs2[tid] = b2[tid];
    __syncthreads();

    int p  = blockIdx.x * 256 + tid;
    int bb = p >> 14;
    int t  = p & (TLEN - 1);

    float sk[RC];
#pragma unroll
    for (int i = 0; i < RC; i++) sk[i] = skip[(size_t)i * NPOS + p];

    float u[RC];
#pragma unroll
    for (int o = 0; o < RC; o++) {
        float acc = bs1[o];
#pragma unroll
        for (int i = 0; i < RC; i++) acc = fmaf(ws1[o * RC + i], sk[i], acc);
        u[o] = fmaxf(acc, 0.0f);
    }

    float* op = out + ((size_t)bb * COUT) * TLEN + t;
    for (int og = 0; og < COUT / 16; og++) {
        int o0 = og * 16;
        u64 acc[8];
#pragma unroll
        for (int q = 0; q < 8; q++) acc[q] = pack2(bs2[o0 + 2*q], bs2[o0 + 2*q + 1]);
#pragma unroll 8
        for (int i = 0; i < RC; i++) {
            u64 ud = dup2(u[i]);
            const ulonglong2* wp = (const ulonglong2*)&ws2t[i][o0];
#pragma unroll
            for (int q2 = 0; q2 < 4; q2++) {
                ulonglong2 wv = wp[q2];
                FFMA2(acc[2*q2],   wv.x, ud);
                FFMA2(acc[2*q2+1], wv.y, ud);
            }
        }
#pragma unroll
        for (int q = 0; q < 8; q++) {
            float v0, v1;
            unpack2(acc[q], v0, v1);
            op[(size_t)(o0 + 2*q)     * TLEN] = v0;
            op[(size_t)(o0 + 2*q + 1) * TLEN] = v1;
        }
    }
}

// ---------------------------------------------------------------------------
extern "C" void kernel_launch(void* const* d_in, const int* in_sizes, int n_in,
                              void* d_out, int out_size)
{
    const float* x      = (const float*)d_in[0];
    const float* in_w   = (const float*)d_in[1];
    const float* in_b   = (const float*)d_in[2];
    const float* conv_w = (const float*)d_in[3];
    const float* conv_b = (const float*)d_in[4];
    const float* gate_w = (const float*)d_in[5];
    const float* gate_b = (const float*)d_in[6];
    const float* res_w  = (const float*)d_in[7];
    const float* res_b  = (const float*)d_in[8];
    const float* skip_w = (const float*)d_in[9];
    const float* skip_b = (const float*)d_in[10];
    const float* s1_w   = (const float*)d_in[11];
    const float* s1_b   = (const float*)d_in[12];
    const float* s2_w   = (const float*)d_in[13];
    const float* s2_b   = (const float*)d_in[14];
    float* out = (float*)d_out;

    float* hbase = nullptr;
    float* skp   = nullptr;
    cudaGetSymbolAddress((void**)&hbase, g_h);
    cudaGetSymbolAddress((void**)&skp, g_skip);

    k_input<<<NPOS/256, 256>>>(x, in_w, in_b, hbase);

    int cur = 0;
    for (int i = 0; i < NLAYERS; i++) {
        int dd = 1 << (i % 10);
        const float* hin = hbase + (size_t)cur * RC * NPOS;
        float* hout      = hbase + (size_t)(cur ^ 1) * RC * NPOS;
        k_layer<<<LGRID, 256>>>(hin, hout, skp,
                                conv_w + (size_t)i * RC * RC * 2, conv_b + i * RC,
                                gate_w + (size_t)i * RC * RC * 2, gate_b + i * RC,
                                res_w  + (size_t)i * RC * RC,     res_b  + i * RC,
                                skip_w + (size_t)i * RC * RC,     skip_b + i * RC,
                                dd, (i == 0) ? 1 : 0);
        cur ^= 1;
    }

    k_final<<<NPOS/256, 256>>>(skp, s1_w, s1_b, s2_w, s2_b, out);
}

// round 8
// speedup vs baseline: 1.5986x; 1.5986x over previous
#include <cuda_runtime.h>
#include <cstdint>

#define BATCH   8
#define TLEN    16384
#define NPOS    (BATCH*TLEN)     // 131072
#define RC      32
#define CIN     256
#define COUT    256
#define NLAYERS 40
#define TP      128              // positions per tile (MMA M)
#define TPB     2                // tiles per block
#define LGRID   (NPOS/(TP*TPB))  // 512

typedef unsigned int u32;
typedef unsigned long long u64;

// Persistent scratch, POSITION-major: h[pos][ch]
__device__ float g_h[2][(size_t)NPOS * RC];
__device__ float g_skip[(size_t)NPOS * RC];

// ---- dynamic smem layout (u32 units). Pitches chosen for conflict-free LDS:
//   X / W1 pitch 36 (bank = 4*row + tig patterns), W2 pitch 20.
#define XHI    0
#define XLO    (XHI  + 128*36)   // 4608
#define W1HI   (XLO  + 128*36)   // 9216
#define W1LO   (W1HI + 64*36)    // 11520
#define W2HI   (W1LO + 64*36)    // 13824
#define W2LO   (W2HI + 64*20)    // 15104
#define SBIAS  (W2LO + 64*20)    // 16384
#define SMEM_U32   (SBIAS + 128) // 16512
#define SMEM_BYTES (SMEM_U32*4)  // 66048

// ---- helpers ---------------------------------------------------------------
// pack {lo_val -> low 16b, hi_val -> high 16b} as bf16x2
__device__ __forceinline__ u32 pack_bf2(float lo, float hi) {
    u32 r; asm("cvt.rn.bf16x2.f32 %0, %1, %2;" : "=r"(r) : "f"(hi), "f"(lo)); return r;
}
__device__ __forceinline__ float bflo_f(u32 u) { return __uint_as_float(u << 16); }
__device__ __forceinline__ float bfhi_f(u32 u) { return __uint_as_float(u & 0xFFFF0000u); }

// D(16x8,f32) += A(16x16,bf16 row) * B(16x8,bf16 col)
__device__ __forceinline__ void mma16816(float* c, const u32* a, u32 b0, u32 b1) {
    asm volatile(
        "mma.sync.aligned.m16n8k16.row.col.f32.bf16.bf16.f32 "
        "{%0,%1,%2,%3}, {%4,%5,%6,%7}, {%8,%9}, {%0,%1,%2,%3};"
        : "+f"(c[0]), "+f"(c[1]), "+f"(c[2]), "+f"(c[3])
        : "r"(a[0]), "r"(a[1]), "r"(a[2]), "r"(a[3]), "r"(b0), "r"(b1));
}

__device__ __forceinline__ float htanh(float x) {
    float y; asm("tanh.approx.f32 %0, %1;" : "=f"(y) : "f"(x)); return y;
}
// tanh(c)*sigmoid(g) = 0.5*tanh(c)*(1 + tanh(g/2))
__device__ __forceinline__ float gated(float c, float g) {
    float t1 = htanh(c);
    float t2 = htanh(0.5f * g);
    float ht = 0.5f * t1;
    return fmaf(ht, t2, ht);
}

// FFMA2 utilities (head/tail kernels)
__device__ __forceinline__ u64 pack2f(float lo, float hi) {
    u64 r; asm("mov.b64 %0, {%1, %2};" : "=l"(r) : "f"(lo), "f"(hi)); return r;
}
__device__ __forceinline__ u64 dup2f(float x) {
    u64 r; asm("mov.b64 %0, {%1, %1};" : "=l"(r) : "f"(x)); return r;
}
__device__ __forceinline__ void unpack2f(u64 v, float& lo, float& hi) {
    asm("mov.b64 {%0, %1}, %2;" : "=f"(lo), "=f"(hi) : "l"(v));
}
#define FFMA2(d, a, b) asm("fma.rn.f32x2 %0, %1, %2, %0;" : "+l"(d) : "l"(a), "l"(b))

// ---------------------------------------------------------------------------
// Input 1x1 conv: h[pos][ch] = in_w[32,256] @ x + in_b  (position-major out)
// ---------------------------------------------------------------------------
__global__ __launch_bounds__(256) void k_input(
    const float* __restrict__ x, const float* __restrict__ w,
    const float* __restrict__ b, float* __restrict__ hout)
{
    __shared__ float ws[CIN][RC];
    __shared__ float bs[RC];
    int tid = threadIdx.x;
    for (int idx = tid; idx < CIN * RC; idx += 256) {
        int o = idx / CIN, ic = idx % CIN;
        ws[ic][o] = w[idx];
    }
    if (tid < RC) bs[tid] = b[tid];
    __syncthreads();

    int p  = blockIdx.x * 256 + tid;
    int bb = p >> 14;
    int t  = p & (TLEN - 1);
    const float* xp = x + ((size_t)bb * CIN) * TLEN + t;

    u64 acc[16];
#pragma unroll
    for (int q = 0; q < 16; q++) acc[q] = pack2f(bs[2*q], bs[2*q+1]);

#pragma unroll 4
    for (int ic = 0; ic < CIN; ic++) {
        float xv = __ldg(xp + (size_t)ic * TLEN);
        u64 xd = dup2f(xv);
        const ulonglong2* wp = (const ulonglong2*)ws[ic];
#pragma unroll
        for (int q = 0; q < 8; q++) {
            ulonglong2 wv = wp[q];
            FFMA2(acc[2*q],   wv.x, xd);
            FFMA2(acc[2*q+1], wv.y, xd);
        }
    }
    float* hp = hout + (size_t)p * RC;
#pragma unroll
    for (int q = 0; q < 8; q++) {
        float4 v;
        unpack2f(acc[2*q],   v.x, v.y);
        unpack2f(acc[2*q+1], v.z, v.w);
        ((float4*)hp)[q] = v;
    }
}

// ---------------------------------------------------------------------------
// Residual layer on HMMA (mma.sync bf16, bf16x3 fp32 emulation).
// Block 256 thr = 8 warps; tile = 128 positions; warp w -> rows [16w,16w+16).
// GEMM1: D1[128, 64] = X[128, K=64]*W1^T  (K = 2*ch + tap; tap0=prev, tap1=cur)
// GEMM2: D2[128, 64] = A[128, 32]*W2^T    (outs: 0-31 res, 32-63 skip)
// ---------------------------------------------------------------------------
__global__ __launch_bounds__(256) void k_layer(
    const float* __restrict__ hin, float* __restrict__ hout,
    float* __restrict__ skip,
    const float* __restrict__ cw, const float* __restrict__ cb,
    const float* __restrict__ gw, const float* __restrict__ gb,
    const float* __restrict__ rw, const float* __restrict__ rb,
    const float* __restrict__ sw, const float* __restrict__ sb,
    int d, int first)
{
    extern __shared__ u32 smem[];
    int tid  = threadIdx.x;
    int wid  = tid >> 5, lane = tid & 31;
    int g    = lane >> 2, tig = lane & 3;

    // ---- stage weights + biases once per block ----
    {
        int o = tid >> 2, q = tid & 3;   // o: output row 0..63, q: quarter of K
        // W1 row o: 64 floats; source linear index == k = 2*ch+tap (cw is [o][ch][tap])
        const float* s1 = (o < 32 ? cw + (size_t)o * 64 : gw + (size_t)(o - 32) * 64) + q * 16;
        float v[16];
#pragma unroll
        for (int j = 0; j < 4; j++) *(float4*)(v + 4*j) = __ldg((const float4*)s1 + j);
        u32* h1 = smem + W1HI + o * 36 + q * 8;
        u32* l1 = smem + W1LO + o * 36 + q * 8;
#pragma unroll
        for (int j = 0; j < 8; j++) {
            u32 hp = pack_bf2(v[2*j], v[2*j+1]);
            h1[j] = hp;
            l1[j] = pack_bf2(v[2*j] - bflo_f(hp), v[2*j+1] - bfhi_f(hp));
        }
        // W2 row o: 32 floats
        const float* s2 = (o < 32 ? rw + (size_t)o * 32 : sw + (size_t)(o - 32) * 32) + q * 8;
        float v2[8];
#pragma unroll
        for (int j = 0; j < 2; j++) *(float4*)(v2 + 4*j) = __ldg((const float4*)s2 + j);
        u32* h2 = smem + W2HI + o * 20 + q * 4;
        u32* l2 = smem + W2LO + o * 20 + q * 4;
#pragma unroll
        for (int j = 0; j < 4; j++) {
            u32 hp = pack_bf2(v2[2*j], v2[2*j+1]);
            h2[j] = hp;
            l2[j] = pack_bf2(v2[2*j] - bflo_f(hp), v2[2*j+1] - bfhi_f(hp));
        }
    }
    if (tid < 128) {
        float bv = (tid < 32) ? __ldg(cb + tid)
                 : (tid < 64) ? __ldg(gb + tid - 32)
                 : (tid < 96) ? __ldg(rb + tid - 64)
                              : __ldg(sb + tid - 96);
        smem[SBIAS + tid] = __float_as_uint(bv);
    }
    const float* sbias = (const float*)(smem + SBIAS);

    int m0 = wid * 16;

    for (int tt = 0; tt < TPB; tt++) {
        int base = (blockIdx.x * TPB + tt) * TP;

        // ---- stage X tile: 2 threads per position, 16 channels each ----
        {
            int pl = tid >> 1, half = tid & 1;
            int pos = base + pl;
            const float* cp = hin + (size_t)pos * RC + half * 16;
            float xc[16], xq[16];
#pragma unroll
            for (int j = 0; j < 4; j++) *(float4*)(xc + 4*j) = __ldg((const float4*)cp + j);
            bool hasp = ((pos & (TLEN - 1)) >= d);
            const float* pp = hin + (size_t)(pos - d) * RC + half * 16;
#pragma unroll
            for (int j = 0; j < 4; j++) {
                float4 z = make_float4(0.f, 0.f, 0.f, 0.f);
                if (hasp) z = __ldg((const float4*)pp + j);
                *(float4*)(xq + 4*j) = z;
            }
            u32* hx = smem + XHI + pl * 36 + half * 16;
            u32* lx = smem + XLO + pl * 36 + half * 16;
#pragma unroll
            for (int ch = 0; ch < 16; ch++) {
                u32 hp = pack_bf2(xq[ch], xc[ch]);   // low = prev (k even), high = cur
                hx[ch] = hp;
                lx[ch] = pack_bf2(xq[ch] - bflo_f(hp), xc[ch] - bfhi_f(hp));
            }
        }
        __syncthreads();

        // ---- GEMM1: 8 n-tiles, 4 k-steps, 3 emulation passes ----
        float acc1[8][4];
#pragma unroll
        for (int nt = 0; nt < 8; nt++) {
            float b0 = sbias[nt*8 + 2*tig], b1 = sbias[nt*8 + 2*tig + 1];
            acc1[nt][0] = b0; acc1[nt][1] = b1; acc1[nt][2] = b0; acc1[nt][3] = b1;
        }
        {
            u32 r0 = (u32)(m0 + g) * 36, r1 = (u32)(m0 + g + 8) * 36;
#pragma unroll
            for (int ks = 0; ks < 4; ks++) {
                int ci = ks * 8 + tig;
                u32 ahi[4] = { smem[XHI + r0 + ci],     smem[XHI + r1 + ci],
                               smem[XHI + r0 + ci + 4], smem[XHI + r1 + ci + 4] };
                u32 alo[4] = { smem[XLO + r0 + ci],     smem[XLO + r1 + ci],
                               smem[XLO + r0 + ci + 4], smem[XLO + r1 + ci + 4] };
#pragma unroll
                for (int nt = 0; nt < 8; nt++) {
                    u32 wb = (u32)(nt*8 + g) * 36 + ci;
                    u32 bh0 = smem[W1HI + wb], bh1 = smem[W1HI + wb + 4];
                    u32 bl0 = smem[W1LO + wb], bl1 = smem[W1LO + wb + 4];
                    mma16816(acc1[nt], ahi, bh0, bh1);
                    mma16816(acc1[nt], alo, bh0, bh1);
                    mma16816(acc1[nt], ahi, bl0, bl1);
                }
            }
        }

        // ---- gated activation -> GEMM2 A fragments (register-local!) ----
        // D1 fragment of conv-ntile nt == A2 fragment slot for chans nt*8+...
        u32 a2h[2][4], a2l[2][4];
        float afv[4][4];                       // keep for nothing else; regs
#pragma unroll
        for (int nt = 0; nt < 4; nt++) {
#pragma unroll
            for (int j = 0; j < 4; j++)
                afv[nt][j] = gated(acc1[nt][j], acc1[nt + 4][j]);
            int ks2 = nt >> 1, off = (nt & 1) * 2;
            u32 h0 = pack_bf2(afv[nt][0], afv[nt][1]);   // row g,  chans 2tig,2tig+1
            u32 h1 = pack_bf2(afv[nt][2], afv[nt][3]);   // row g+8
            a2h[ks2][off]     = h0;
            a2h[ks2][off + 1] = h1;
            a2l[ks2][off]     = pack_bf2(afv[nt][0] - bflo_f(h0), afv[nt][1] - bfhi_f(h0));
            a2l[ks2][off + 1] = pack_bf2(afv[nt][2] - bflo_f(h1), afv[nt][3] - bfhi_f(h1));
        }

        // ---- GEMM2: 8 n-tiles (res|skip), 2 k-steps, 3 passes ----
        float acc2[8][4];
#pragma unroll
        for (int nt = 0; nt < 8; nt++) {
            float b0 = sbias[64 + nt*8 + 2*tig], b1 = sbias[64 + nt*8 + 2*tig + 1];
            acc2[nt][0] = b0; acc2[nt][1] = b1; acc2[nt][2] = b0; acc2[nt][3] = b1;
        }
#pragma unroll
        for (int ks = 0; ks < 2; ks++) {
#pragma unroll
            for (int nt = 0; nt < 8; nt++) {
                u32 wb = (u32)(nt*8 + g) * 20 + ks * 8 + tig;
                u32 bh0 = smem[W2HI + wb], bh1 = smem[W2HI + wb + 4];
                u32 bl0 = smem[W2LO + wb], bl1 = smem[W2LO + wb + 4];
                mma16816(acc2[nt], a2h[ks], bh0, bh1);
                mma16816(acc2[nt], a2l[ks], bh0, bh1);
                mma16816(acc2[nt], a2h[ks], bl0, bl1);
            }
        }

        // ---- writeback: hout = h + res, skip (+)= s ----
#pragma unroll
        for (int nt = 0; nt < 4; nt++) {
            int ch = nt * 8 + 2 * tig;
#pragma unroll
            for (int rr = 0; rr < 2; rr++) {
                int pos = base + m0 + g + rr * 8;
                size_t idx = (size_t)pos * RC + ch;
                float2 xc = *(const float2*)(hin + idx);
                float r0 = acc2[nt][rr*2], r1 = acc2[nt][rr*2 + 1];
                float s0 = acc2[nt + 4][rr*2], s1 = acc2[nt + 4][rr*2 + 1];
                if (!first) {
                    float2 os = *(const float2*)(skip + idx);
                    s0 += os.x; s1 += os.y;
                }
                *(float2*)(hout + idx) = make_float2(xc.x + r0, xc.y + r1);
                *(float2*)(skip + idx) = make_float2(s0, s1);
            }
        }
        __syncthreads();   // protect sX before next tile restage
    }
}

// ---------------------------------------------------------------------------
// Output head: out = s2( relu(s1(skip)) ), skip position-major, out [B][256][T]
// ---------------------------------------------------------------------------
__global__ __launch_bounds__(256) void k_final(
    const float* __restrict__ skip,
    const float* __restrict__ w1, const float* __restrict__ b1,
    const float* __restrict__ w2, const float* __restrict__ b2,
    float* __restrict__ out)
{
    __shared__ float ws1[RC * RC];
    __shared__ float ws2t[RC][COUT];
    __shared__ float bs1[RC];
    __shared__ float bs2[COUT];
    int tid = threadIdx.x;
    for (int idx = tid; idx < RC * RC; idx += 256) ws1[idx] = w1[idx];
    for (int idx = tid; idx < COUT * RC; idx += 256) {
        int o = idx / RC, i = idx % RC;
        ws2t[i][o] = w2[idx];
    }
    if (tid < RC) bs1[tid] = b1[tid];
    if (tid < COUT) bs2[tid] = b2[tid];
    __syncthreads();

    int p  = blockIdx.x * 256 + tid;
    int bb = p >> 14;
    int t  = p & (TLEN - 1);

    float sk[RC];
    const float4* sp = (const float4*)(skip + (size_t)p * RC);
#pragma unroll
    for (int q = 0; q < 8; q++) *(float4*)(sk + 4*q) = __ldg(sp + q);

    float u[RC];
#pragma unroll
    for (int o = 0; o < RC; o++) {
        float acc = bs1[o];
#pragma unroll
        for (int i = 0; i < RC; i++) acc = fmaf(ws1[o * RC + i], sk[i], acc);
        u[o] = fmaxf(acc, 0.0f);
    }

    float* op = out + ((size_t)bb * COUT) * TLEN + t;
    for (int og = 0; og < COUT / 16; og++) {
        int o0 = og * 16;
        u64 acc[8];
#pragma unroll
        for (int q = 0; q < 8; q++) acc[q] = pack2f(bs2[o0 + 2*q], bs2[o0 + 2*q + 1]);
#pragma unroll 8
        for (int i = 0; i < RC; i++) {
            u64 ud = dup2f(u[i]);
            const ulonglong2* wp = (const ulonglong2*)&ws2t[i][o0];
#pragma unroll
            for (int q2 = 0; q2 < 4; q2++) {
                ulonglong2 wv = wp[q2];
                FFMA2(acc[2*q2],   wv.x, ud);
                FFMA2(acc[2*q2+1], wv.y, ud);
            }
        }
#pragma unroll
        for (int q = 0; q < 8; q++) {
            float v0, v1;
            unpack2f(acc[q], v0, v1);
            op[(size_t)(o0 + 2*q)     * TLEN] = v0;
            op[(size_t)(o0 + 2*q + 1) * TLEN] = v1;
        }
    }
}

// ---------------------------------------------------------------------------
extern "C" void kernel_launch(void* const* d_in, const int* in_sizes, int n_in,
                              void* d_out, int out_size)
{
    const float* x      = (const float*)d_in[0];
    const float* in_w   = (const float*)d_in[1];
    const float* in_b   = (const float*)d_in[2];
    const float* conv_w = (const float*)d_in[3];
    const float* conv_b = (const float*)d_in[4];
    const float* gate_w = (const float*)d_in[5];
    const float* gate_b = (const float*)d_in[6];
    const float* res_w  = (const float*)d_in[7];
    const float* res_b  = (const float*)d_in[8];
    const float* skip_w = (const float*)d_in[9];
    const float* skip_b = (const float*)d_in[10];
    const float* s1_w   = (const float*)d_in[11];
    const float* s1_b   = (const float*)d_in[12];
    const float* s2_w   = (const float*)d_in[13];
    const float* s2_b   = (const float*)d_in[14];
    float* out = (float*)d_out;

    float* hbase = nullptr;
    float* skp   = nullptr;
    cudaGetSymbolAddress((void**)&hbase, g_h);
    cudaGetSymbolAddress((void**)&skp, g_skip);

    cudaFuncSetAttribute(k_layer, cudaFuncAttributeMaxDynamicSharedMemorySize, SMEM_BYTES);

    k_input<<<NPOS/256, 256>>>(x, in_w, in_b, hbase);

    int cur = 0;
    for (int i = 0; i < NLAYERS; i++) {
        int dd = 1 << (i % 10);
        const float* hin = hbase + (size_t)cur * NPOS * RC;
        float* hout      = hbase + (size_t)(cur ^ 1) * NPOS * RC;
        k_layer<<<LGRID, 256, SMEM_BYTES>>>(hin, hout, skp,
                                conv_w + (size_t)i * RC * RC * 2, conv_b + i * RC,
                                gate_w + (size_t)i * RC * RC * 2, gate_b + i * RC,
                                res_w  + (size_t)i * RC * RC,     res_b  + i * RC,
                                skip_w + (size_t)i * RC * RC,     skip_b + i * RC,
                                dd, (i == 0) ? 1 : 0);
        cur ^= 1;
    }

    k_final<<<NPOS/256, 256>>>(skp, s1_w, s1_b, s2_w, s2_b, out);
}